// round 16
// baseline (speedup 1.0000x reference)
#include <cuda_runtime.h>

#define BB 512
#define TT 512
#define DD 128
#define LL 256
#define G4 1024
#define NCTA 128
#define NTHR 512
#define NRB 4            // row blocks
#define RBCTA 32         // CTAs per row-block barrier group

typedef unsigned long long ull;

// Persistent state (static __device__ globals — no allocation)
__device__ float g_H[3][LL][BB];          // hidden state [feature][batch], TRIPLE buffered
__device__ float g_encT[TT][DD][BB];      // encoder inputs transposed
__device__ float g_x0T[DD][BB];           // decoder x(0) transposed
__device__ unsigned int g_count[NRB * 32];  // one counter per 128B
__device__ unsigned int g_gen[NRB * 32];    // monotonic generation

// Split barrier over the 32 CTAs of one row block. Snapshot-based (replay-safe).
__device__ __forceinline__ void rb_arrive(int rb, unsigned int* snap) {
    __syncthreads();                     // all CTA work done before arriving
    if (threadIdx.x == 0) {
        volatile unsigned int* gp = &g_gen[rb * 32];
        *snap = *gp;                     // snapshot BEFORE own arrive
        __threadfence();
        if (atomicAdd(&g_count[rb * 32], 1u) == RBCTA - 1u) {
            g_count[rb * 32] = 0u;
            __threadfence();
            atomicAdd(&g_gen[rb * 32], 1u);   // release
        }
    }
}
__device__ __forceinline__ void rb_wait(int rb, unsigned int snap) {
    if (threadIdx.x == 0) {
        volatile unsigned int* gp = &g_gen[rb * 32];
        while (*gp == snap) { }
        __threadfence();
    }
    __syncthreads();
}

__device__ __forceinline__ float sigm(float x) { return 1.0f / (1.0f + __expf(-x)); }

__device__ __forceinline__ ull pack2(float lo, float hi) {
    ull r; asm("mov.b64 %0, {%1, %2};" : "=l"(r) : "f"(lo), "f"(hi)); return r;
}
__device__ __forceinline__ void unpack2(ull v, float& lo, float& hi) {
    asm("mov.b64 {%0, %1}, %2;" : "=f"(lo), "=f"(hi) : "l"(v));
}
__device__ __forceinline__ void ffma2(ull& d, ull a, ull b) {
    asm("fma.rn.f32x2 %0, %1, %2, %0;" : "+l"(d) : "l"(a), "l"(b));
}

// COLUMN-PAIR packing: acc[i][jp] = {col 2jp, col 2jp+1} of row i.
// W pairs load DIRECTLY as ulonglong2 from smem (no dup movs); only 4 A-dups per k.
// Warp subtile is 64 rows x 16 cols: lanes 16-31 duplicate lanes 0-15's A
// addresses -> coalescer dedups -> 2 L1 wavefronts per LDG.128 (was 4).
__device__ __forceinline__ void gemm48(
    const float* __restrict__ A,
    const float* __restrict__ w,      // pre-offset to this thread's 8 cols (smem, stride 32)
    int kcnt, ull acc[4][4])
{
    #pragma unroll 8
    for (int k = 0; k < kcnt; k++) {
        float4 av = *reinterpret_cast<const float4*>(A + (size_t)k * BB);
        ulonglong2 wlo = *reinterpret_cast<const ulonglong2*>(w + k * 32);
        ulonglong2 whi = *reinterpret_cast<const ulonglong2*>(w + k * 32 + 4);
        ull a0 = pack2(av.x, av.x);
        ull a1 = pack2(av.y, av.y);
        ull a2 = pack2(av.z, av.z);
        ull a3 = pack2(av.w, av.w);
        ffma2(acc[0][0], a0, wlo.x);
        ffma2(acc[0][1], a0, wlo.y);
        ffma2(acc[0][2], a0, whi.x);
        ffma2(acc[0][3], a0, whi.y);
        ffma2(acc[1][0], a1, wlo.x);
        ffma2(acc[1][1], a1, wlo.y);
        ffma2(acc[1][2], a1, whi.x);
        ffma2(acc[1][3], a1, whi.y);
        ffma2(acc[2][0], a2, wlo.x);
        ffma2(acc[2][1], a2, wlo.y);
        ffma2(acc[2][2], a2, whi.x);
        ffma2(acc[2][3], a2, whi.y);
        ffma2(acc[3][0], a3, wlo.x);
        ffma2(acc[3][1], a3, wlo.y);
        ffma2(acc[3][2], a3, whi.x);
        ffma2(acc[3][3], a3, whi.y);
    }
}

// Same but weights streamed from GLOBAL memory (stride G4). Used once (decoder t=0).
__device__ __forceinline__ void gemm48g(
    const float* __restrict__ A,
    const float* __restrict__ wg,     // pre-offset to this thread's 8 gmem cols (32B-aligned)
    int kcnt, ull acc[4][4])
{
    #pragma unroll 4
    for (int k = 0; k < kcnt; k++) {
        float4 av = *reinterpret_cast<const float4*>(A + (size_t)k * BB);
        ulonglong2 wlo = *reinterpret_cast<const ulonglong2*>(wg + (size_t)k * G4);
        ulonglong2 whi = *reinterpret_cast<const ulonglong2*>(wg + (size_t)k * G4 + 4);
        ull a0 = pack2(av.x, av.x);
        ull a1 = pack2(av.y, av.y);
        ull a2 = pack2(av.z, av.z);
        ull a3 = pack2(av.w, av.w);
        ffma2(acc[0][0], a0, wlo.x);
        ffma2(acc[0][1], a0, wlo.y);
        ffma2(acc[0][2], a0, whi.x);
        ffma2(acc[0][3], a0, whi.y);
        ffma2(acc[1][0], a1, wlo.x);
        ffma2(acc[1][1], a1, wlo.y);
        ffma2(acc[1][2], a1, whi.x);
        ffma2(acc[1][3], a1, whi.y);
        ffma2(acc[2][0], a2, wlo.x);
        ffma2(acc[2][1], a2, wlo.y);
        ffma2(acc[2][2], a2, whi.x);
        ffma2(acc[2][3], a2, whi.y);
        ffma2(acc[3][0], a3, wlo.x);
        ffma2(acc[3][1], a3, wlo.y);
        ffma2(acc[3][2], a3, whi.x);
        ffma2(acc[3][3], a3, whi.y);
    }
}

__device__ __forceinline__ void acc_zero(ull acc[4][4]) {
    #pragma unroll
    for (int i = 0; i < 4; i++)
        #pragma unroll
        for (int j = 0; j < 4; j++)
            acc[i][j] = 0ull;
}

// XOR-swizzled partial-z store: z(row,c) at row*32 + (c ^ ((row>>2)&15)).
// tx = (row>>2)&15 for this thread's 4 rows; 2-way conflict across th halves.
__device__ __forceinline__ void z_store(float* zs, int rowBase, int tx, int cbase,
                                        const ull acc[4][4]) {
    #pragma unroll
    for (int i = 0; i < 4; i++) {
        float* zrow = zs + (rowBase + tx * 4 + i) * 32;
        #pragma unroll
        for (int jp = 0; jp < 4; jp++) {
            float lo, hi;
            unpack2(acc[i][jp], lo, hi);
            int c = cbase + jp * 2;
            zrow[c ^ tx] = lo;
            zrow[(c + 1) ^ tx] = hi;
        }
    }
}

// activation: thread -> (2 rows, 1 unit); FIXED mapping (c lives here)
__device__ __forceinline__ void activation(
    const float* __restrict__ zsm, const float* __restrict__ bsm,
    float c2[2], float* __restrict__ hOutT, int b0, int nb, int tid)
{
    int u  = tid >> 6;              // 0..7
    int r0 = (tid & 63) * 2;
    float hv[2];
    #pragma unroll
    for (int i = 0; i < 2; i++) {
        int r = r0 + i;
        int sw = (r >> 2) & 15;     // read-side of the XOR swizzle (4-bit, matches tx)
        float zi = bsm[u],      zf = bsm[8 + u];
        float zg = bsm[16 + u], zo = bsm[24 + u];
        #pragma unroll
        for (int p = 0; p < 4; p++) {
            const float* zp = zsm + p * (128 * 32) + r * 32;
            zi += zp[u ^ sw];
            zf += zp[(8 + u) ^ sw];
            zg += zp[(16 + u) ^ sw];
            zo += zp[(24 + u) ^ sw];
        }
        float ig = sigm(zi);
        float fg = sigm(zf);
        float gg = fmaxf(zg, 0.0f);
        float og = sigm(zo);
        float cn = fg * c2[i] + ig * gg;
        c2[i] = cn;
        hv[i] = og * fmaxf(cn, 0.0f);
    }
    *reinterpret_cast<float2*>(&hOutT[(nb * 8 + u) * BB + b0 + r0]) =
        make_float2(hv[0], hv[1]);
}

// out(tt) = h@Wo + bo : 4 out-cols x 128 rows, K split in 4 chunks, zsm scratch
__device__ __forceinline__ void outproj(
    const float* __restrict__ hbuf,   // &g_H[p][0][0] (all-visible h)
    const float* __restrict__ wosm, const float* __restrict__ bosm,
    float* __restrict__ zsm, float* __restrict__ outp,
    int b0, int nb, int tt, int tid)
{
    int b  = tid & 127;
    int qq = tid >> 7;                     // 0..3 -> K chunk of 64
    const float* hP = hbuf + (size_t)(qq * 64) * BB + b0 + b;
    const float* wP = wosm + qq * 64 * 4;
    float s0 = 0.f, s1 = 0.f, s2 = 0.f, s3 = 0.f;
    #pragma unroll 8
    for (int kk = 0; kk < 64; kk++) {
        float h = hP[(size_t)kk * BB];
        float4 w4 = *reinterpret_cast<const float4*>(wP + kk * 4);
        s0 = fmaf(h, w4.x, s0);
        s1 = fmaf(h, w4.y, s1);
        s2 = fmaf(h, w4.z, s2);
        s3 = fmaf(h, w4.w, s3);
    }
    if (qq) {
        float* zp = zsm + ((qq - 1) * 128 + b) * 4;
        zp[0] = s0; zp[1] = s1; zp[2] = s2; zp[3] = s3;
    }
    __syncthreads();
    if (qq == 0) {
        #pragma unroll
        for (int p = 0; p < 3; p++) {
            const float* zp = zsm + (p * 128 + b) * 4;
            s0 += zp[0]; s1 += zp[1]; s2 += zp[2]; s3 += zp[3];
        }
        s0 += bosm[0]; s1 += bosm[1]; s2 += bosm[2]; s3 += bosm[3];
        *reinterpret_cast<float4*>(
            outp + (size_t)(b0 + b) * (TT * DD) + tt * DD + nb * 4) =
            make_float4(s0, s1, s2, s3);
    }
}

// Tiled transpose: encIn[b][t][k] -> g_encT[t][k][b]
extern "C" __global__ void __launch_bounds__(256)
transpose_enc_kernel(const float* __restrict__ in)
{
    __shared__ float tile[32][33];
    int t  = blockIdx.z;
    int k0 = blockIdx.y * 32;
    int b0 = blockIdx.x * 32;
    int tx = threadIdx.x, ty = threadIdx.y;  // 32 x 8
    #pragma unroll
    for (int i = 0; i < 32; i += 8)
        tile[ty + i][tx] = in[(size_t)(b0 + ty + i) * (TT * DD) + t * DD + k0 + tx];
    __syncthreads();
    #pragma unroll
    for (int i = 0; i < 32; i += 8)
        g_encT[t][k0 + ty + i][b0 + tx] = tile[tx][ty + i];
}

extern "C" __global__ void __launch_bounds__(NTHR, 1)
lstm_ae_kernel(const float* __restrict__ decIn,
               const float* __restrict__ W0, const float* __restrict__ U0, const float* __restrict__ b0g,
               const float* __restrict__ W1, const float* __restrict__ U1, const float* __restrict__ b1g,
               const float* __restrict__ Wd, const float* __restrict__ Ud, const float* __restrict__ bdg,
               const float* __restrict__ Wo, const float* __restrict__ bog,
               float* __restrict__ outp)
{
    extern __shared__ float smem[];
    float* w0sm  = smem;                  // [384][32]
    float* w1sm  = w0sm + 384 * 32;       // [256][32]  (W1+U1 fused)
    float* wdxsm = w1sm + 256 * 32;       // [128][32]  x-part of Wd (decoder t=0 only)
    float* wfdsm = wdxsm + 128 * 32;      // [256][32]  FUSED Wo@Wd + Ud
    float* wosm  = wfdsm + 256 * 32;      // [256][4]
    float* b0sm  = wosm + 256 * 4;        // 32
    float* b1sm  = b0sm + 32;             // 32
    float* bdsm  = b1sm + 32;             // 32  (plain bd, t=0)
    float* bfdsm = bdsm + 32;             // 32  (bo@Wd + bd, t>=1)
    float* bosm  = bfdsm + 32;            // 4 (+12 pad)
    float* zsm   = bosm + 16;             // [4][128][32] XOR-swizzled

    int tid = threadIdx.x;
    int nb = blockIdx.x & 31;           // hidden-unit block (8 units)
    int rb = blockIdx.x >> 5;           // row block (128 batch rows)
    int b0 = rb * 128;

    // thread decomposition: quarter q (K), warp subtile = 64 rows x 16 cols
    int q    = tid >> 7;                // K quarter
    int w2   = (tid >> 5) & 3;          // warp within quarter
    int rg   = w2 & 1;                  // row group (64 rows)
    int cg   = w2 >> 1;                 // col group (16 cols)
    int lane = tid & 31;
    int tx   = lane & 15;               // rows tx*4 .. +3 within row group
    int th   = lane >> 4;               // col half (8 cols)
    int cbase = cg * 16 + th * 8;       // local col base (0/8/16/24)
    int rowBase = rg * 64;
    int colBase = b0 + rowBase + tx * 4;
    float* zq = zsm + q * (128 * 32);
    const float* w0ty  = w0sm + cbase;
    const float* w1ty  = w1sm + cbase;
    const float* wdxty = wdxsm + cbase;
    const float* wfdty = wfdsm + cbase;

    // ---- one-time weight preload, layout [k][32 local cols] ----
    for (int idx = tid; idx < 384 * 32; idx += NTHR) {
        int k = idx >> 5, lc = idx & 31;
        int gcol = (lc >> 3) * LL + nb * 8 + (lc & 7);
        w0sm[idx] = (k < DD) ? W0[k * G4 + gcol] : U0[(k - DD) * G4 + gcol];
    }
    for (int idx = tid; idx < 256 * 32; idx += NTHR) {
        int k = idx >> 5, lc = idx & 31;
        int gcol = (lc >> 3) * LL + nb * 8 + (lc & 7);
        w1sm[idx] = W1[k * G4 + gcol] + U1[k * G4 + gcol];
    }
    for (int idx = tid; idx < 128 * 32; idx += NTHR) {
        int k = idx >> 5, lc = idx & 31;
        int gcol = (lc >> 3) * LL + nb * 8 + (lc & 7);
        wdxsm[idx] = Wd[k * G4 + gcol];
    }
    // FUSED decoder weight: Wfd[k][lc] = Ud[k][gcol] + sum_j Wo[k][j]*Wd[j][gcol]
    for (int idx = tid; idx < 256 * 32; idx += NTHR) {
        int k = idx >> 5, lc = idx & 31;
        int gcol = (lc >> 3) * LL + nb * 8 + (lc & 7);
        float s = Ud[k * G4 + gcol];
        const float* worow = Wo + k * DD;
        #pragma unroll 4
        for (int j = 0; j < DD; j++)
            s = fmaf(worow[j], Wd[j * G4 + gcol], s);
        wfdsm[idx] = s;
    }
    for (int idx = tid; idx < 256 * 4; idx += NTHR) {
        int k = idx >> 2, j = idx & 3;
        wosm[idx] = Wo[k * DD + nb * 4 + j];
    }
    if (tid < 32) {
        int gcol = (tid >> 3) * LL + nb * 8 + (tid & 7);
        b0sm[tid] = b0g[gcol];
        b1sm[tid] = b1g[gcol];
        bdsm[tid] = bdg[gcol];
        float s = bdg[gcol];
        #pragma unroll 4
        for (int j = 0; j < DD; j++)
            s = fmaf(bog[j], Wd[j * G4 + gcol], s);
        bfdsm[tid] = s;
    }
    if (tid < 4) bosm[tid] = bog[nb * 4 + tid];

    // init: zero h buffer 0; stage decoder x(0) transposed
    for (int idx = tid; idx < 8 * 128; idx += NTHR) {
        int f = idx >> 7, b = idx & 127;
        g_H[0][nb * 8 + f][b0 + b] = 0.0f;
    }
    for (int idx = tid; idx < 4 * 128; idx += NTHR) {
        int f = idx >> 7, b = idx & 127;
        g_x0T[nb * 4 + f][b0 + b] = decIn[(size_t)(b0 + b) * (TT * DD) + nb * 4 + f];
    }
    __syncthreads();   // weights visible before prologue x-gemm

    float c2[2] = {0.0f, 0.0f};
    unsigned int snap;

    // x-partials for encoder t=0 accumulate in registers (depends only on g_encT)
    ull acc[4][4];
    acc_zero(acc);
    gemm48(&g_encT[0][q * 32][colBase], w0ty + (q * 32) * 32, 32, acc);

    rb_arrive(rb, &snap);   // init barrier (H, x0 visible)

    int cur = 0;
    // ---------------- encoder (triple-buffered h) ----------------
    for (int t = 0; t < TT; t++) {
        int nx;
        // ===== layer 0: acc already holds x_t @ W0 partials =====
        rb_wait(rb, snap);                         // h_L1(t-1) visible
        gemm48(&g_H[cur][q * 64][colBase], w0ty + (DD + q * 64) * 32, 64, acc);
        z_store(zq, rowBase, tx, cbase, acc);
        __syncthreads();
        nx = cur + 1; if (nx == 3) nx = 0;
        activation(zsm, b0sm, c2, &g_H[nx][0][0], b0, nb, tid);
        rb_arrive(rb, &snap);                      // h_L0(t) posted
        cur = nx;

        // ===== layer 1: z = h' @ (W1+U1) =====
        rb_wait(rb, snap);                         // h_L0(t) all visible
        acc_zero(acc);
        gemm48(&g_H[cur][q * 64][colBase], w1ty + (q * 64) * 32, 64, acc);
        z_store(zq, rowBase, tx, cbase, acc);
        __syncthreads();
        nx = cur + 1; if (nx == 3) nx = 0;
        activation(zsm, b1sm, c2, &g_H[nx][0][0], b0, nb, tid);
        rb_arrive(rb, &snap);                      // h_L1(t) posted
        cur = nx;

        // ===== overlap: next step's x-partials in registers while barrier settles
        acc_zero(acc);
        if (t + 1 < TT)
            gemm48(&g_encT[t + 1][q * 32][colBase], w0ty + (q * 32) * 32, 32, acc);
    }

    // ---------------- decoder: ONE barrier per step (fused recurrence) ----------
    // z(t) = h(t-1) @ Wfd + bfd   for t>=1;  t=0 uses x0@Wd + h_enc@Ud + bd.
    for (int t = 0; t < TT; t++) {
        rb_wait(rb, snap);                         // h(t-1) all visible in buf[cur]
        acc_zero(acc);
        if (t == 0) {
            gemm48(&g_x0T[q * 32][colBase], wdxty + (q * 32) * 32, 32, acc);
            gemm48g(&g_H[cur][q * 64][colBase],
                    Ud + (size_t)(q * 64) * G4 + (cbase >> 3) * LL + nb * 8, 64, acc);
        } else {
            gemm48(&g_H[cur][q * 64][colBase], wfdty + (q * 64) * 32, 64, acc);
        }
        z_store(zq, rowBase, tx, cbase, acc);
        __syncthreads();
        int nx = cur + 1; if (nx == 3) nx = 0;
        activation(zsm, (t == 0) ? bdsm : bfdsm, c2, &g_H[nx][0][0], b0, nb, tid);
        rb_arrive(rb, &snap);                      // h(t) posted
        // ===== shadow: out(t-1) = h(t-1)@Wo + bo (buf[cur] still safe: 3 buffers)
        if (t >= 1)
            outproj(&g_H[cur][0][0], wosm, bosm, zsm, outp, b0, nb, t - 1, tid);
        cur = nx;
    }
    // epilogue: out(511) needs all h(511)
    rb_wait(rb, snap);
    outproj(&g_H[cur][0][0], wosm, bosm, zsm, outp, b0, nb, TT - 1, tid);
}

extern "C" void kernel_launch(void* const* d_in, const int* in_sizes, int n_in,
                              void* d_out, int out_size)
{
    const float* encIn = (const float*)d_in[0];
    const float* decIn = (const float*)d_in[1];
    const float* W0    = (const float*)d_in[2];
    const float* U0    = (const float*)d_in[3];
    const float* b0    = (const float*)d_in[4];
    const float* W1    = (const float*)d_in[5];
    const float* U1    = (const float*)d_in[6];
    const float* b1    = (const float*)d_in[7];
    const float* Wd    = (const float*)d_in[8];
    const float* Ud    = (const float*)d_in[9];
    const float* bd    = (const float*)d_in[10];
    const float* Wo    = (const float*)d_in[11];
    const float* bo    = (const float*)d_in[12];
    float* outp = (float*)d_out;

    // 1) transpose encoder inputs
    {
        dim3 grid(BB / 32, DD / 32, TT);
        dim3 block(32, 8);
        transpose_enc_kernel<<<grid, block>>>(encIn);
    }

    // 2) persistent LSTM kernel
    // smem floats: 12288+8192+4096+8192+1024+128+16 + 4*128*32 = 50320 (201.3KB)
    size_t smem_bytes = 50320 * sizeof(float);
    cudaFuncSetAttribute((const void*)lstm_ae_kernel,
                         cudaFuncAttributeMaxDynamicSharedMemorySize, (int)smem_bytes);
    lstm_ae_kernel<<<NCTA, NTHR, smem_bytes>>>(
        decIn, W0, U0, b0, W1, U1, b1, Wd, Ud, bd, Wo, bo, outp);
}

// round 17
// speedup vs baseline: 1.0939x; 1.0939x over previous
#include <cuda_runtime.h>

#define BB 512
#define TT 512
#define DD 128
#define LL 256
#define G4 1024
#define NCTA 128
#define NTHR 512
#define NRB 4            // row blocks
#define RBCTA 32         // CTAs per row-block barrier group

typedef unsigned long long ull;

// Persistent state (static __device__ globals — no allocation)
__device__ float g_H[3][LL][BB];          // hidden state [feature][batch], TRIPLE buffered
__device__ float g_encT[TT][DD][BB];      // encoder inputs transposed
__device__ float g_x0T[DD][BB];           // decoder x(0) transposed
__device__ unsigned int g_count[NRB * 32];  // one counter per 128B
__device__ unsigned int g_gen[NRB * 32];    // monotonic generation

// ---- lean memory-model barrier primitives ----
__device__ __forceinline__ unsigned int ld_relaxed(unsigned int* p) {
    unsigned int v;
    asm volatile("ld.relaxed.gpu.global.u32 %0, [%1];" : "=r"(v) : "l"(p) : "memory");
    return v;
}
__device__ __forceinline__ unsigned int ld_acquire(unsigned int* p) {
    unsigned int v;
    asm volatile("ld.acquire.gpu.global.u32 %0, [%1];" : "=r"(v) : "l"(p) : "memory");
    return v;
}
__device__ __forceinline__ unsigned int atom_acqrel_add(unsigned int* p, unsigned int v) {
    unsigned int old;
    asm volatile("atom.acq_rel.gpu.global.add.u32 %0, [%1], %2;"
                 : "=r"(old) : "l"(p), "r"(v) : "memory");
    return old;
}
__device__ __forceinline__ void st_relaxed(unsigned int* p, unsigned int v) {
    asm volatile("st.relaxed.gpu.global.u32 [%0], %1;" :: "l"(p), "r"(v) : "memory");
}
__device__ __forceinline__ void red_release_add(unsigned int* p, unsigned int v) {
    asm volatile("red.release.gpu.global.add.u32 [%0], %1;" :: "l"(p), "r"(v) : "memory");
}

// Split barrier over the 32 CTAs of one row block. Snapshot-based (replay-safe).
// arrive: syncthreads publishes CTA's stores intra-CTA; thread0's acq_rel arrival
// + releaser's release on gen make them gpu-visible (cumulativity).
__device__ __forceinline__ void rb_arrive(int rb, unsigned int* snap) {
    __syncthreads();                     // all CTA work done before arriving
    if (threadIdx.x == 0) {
        *snap = ld_relaxed(&g_gen[rb * 32]);     // snapshot BEFORE own arrive
        unsigned int old = atom_acqrel_add(&g_count[rb * 32], 1u);
        if (old == RBCTA - 1u) {
            st_relaxed(&g_count[rb * 32], 0u);   // ordered before gen by release below
            red_release_add(&g_gen[rb * 32], 1u);
        }
    }
}
// ALL threads poll with acquire: no trailing __syncthreads, no serialized wakeup.
__device__ __forceinline__ void rb_wait(int rb, unsigned int* snapSm) {
    // snapSm: smem broadcast of thread0's snapshot (written in rb_arrive epilogue)
    unsigned int s = *snapSm;
    while (ld_acquire(&g_gen[rb * 32]) == s) { }
}

__device__ __forceinline__ float sigm(float x) { return 1.0f / (1.0f + __expf(-x)); }

__device__ __forceinline__ ull pack2(float lo, float hi) {
    ull r; asm("mov.b64 %0, {%1, %2};" : "=l"(r) : "f"(lo), "f"(hi)); return r;
}
__device__ __forceinline__ void unpack2(ull v, float& lo, float& hi) {
    asm("mov.b64 {%0, %1}, %2;" : "=f"(lo), "=f"(hi) : "l"(v));
}
__device__ __forceinline__ void ffma2(ull& d, ull a, ull b) {
    asm("fma.rn.f32x2 %0, %1, %2, %0;" : "+l"(d) : "l"(a), "l"(b));
}

// COLUMN-PAIR packing: acc[i][jp] = {col 2jp, col 2jp+1} of row i.
// W pairs load DIRECTLY as ulonglong2 from smem (no dup movs); only 4 A-dups per k.
__device__ __forceinline__ void gemm48(
    const float* __restrict__ A,
    const float* __restrict__ w,      // pre-offset to this thread's 8 cols (smem, stride 32)
    int kcnt, ull acc[4][4])
{
    #pragma unroll 8
    for (int k = 0; k < kcnt; k++) {
        float4 av = *reinterpret_cast<const float4*>(A + (size_t)k * BB);
        ulonglong2 wlo = *reinterpret_cast<const ulonglong2*>(w + k * 32);
        ulonglong2 whi = *reinterpret_cast<const ulonglong2*>(w + k * 32 + 4);
        ull a0 = pack2(av.x, av.x);
        ull a1 = pack2(av.y, av.y);
        ull a2 = pack2(av.z, av.z);
        ull a3 = pack2(av.w, av.w);
        ffma2(acc[0][0], a0, wlo.x);
        ffma2(acc[0][1], a0, wlo.y);
        ffma2(acc[0][2], a0, whi.x);
        ffma2(acc[0][3], a0, whi.y);
        ffma2(acc[1][0], a1, wlo.x);
        ffma2(acc[1][1], a1, wlo.y);
        ffma2(acc[1][2], a1, whi.x);
        ffma2(acc[1][3], a1, whi.y);
        ffma2(acc[2][0], a2, wlo.x);
        ffma2(acc[2][1], a2, wlo.y);
        ffma2(acc[2][2], a2, whi.x);
        ffma2(acc[2][3], a2, whi.y);
        ffma2(acc[3][0], a3, wlo.x);
        ffma2(acc[3][1], a3, wlo.y);
        ffma2(acc[3][2], a3, whi.x);
        ffma2(acc[3][3], a3, whi.y);
    }
}

// Same but weights streamed from GLOBAL memory (stride G4). Used once (decoder t=0).
__device__ __forceinline__ void gemm48g(
    const float* __restrict__ A,
    const float* __restrict__ wg,     // pre-offset to this thread's 8 gmem cols (32B-aligned)
    int kcnt, ull acc[4][4])
{
    #pragma unroll 4
    for (int k = 0; k < kcnt; k++) {
        float4 av = *reinterpret_cast<const float4*>(A + (size_t)k * BB);
        ulonglong2 wlo = *reinterpret_cast<const ulonglong2*>(wg + (size_t)k * G4);
        ulonglong2 whi = *reinterpret_cast<const ulonglong2*>(wg + (size_t)k * G4 + 4);
        ull a0 = pack2(av.x, av.x);
        ull a1 = pack2(av.y, av.y);
        ull a2 = pack2(av.z, av.z);
        ull a3 = pack2(av.w, av.w);
        ffma2(acc[0][0], a0, wlo.x);
        ffma2(acc[0][1], a0, wlo.y);
        ffma2(acc[0][2], a0, whi.x);
        ffma2(acc[0][3], a0, whi.y);
        ffma2(acc[1][0], a1, wlo.x);
        ffma2(acc[1][1], a1, wlo.y);
        ffma2(acc[1][2], a1, whi.x);
        ffma2(acc[1][3], a1, whi.y);
        ffma2(acc[2][0], a2, wlo.x);
        ffma2(acc[2][1], a2, wlo.y);
        ffma2(acc[2][2], a2, whi.x);
        ffma2(acc[2][3], a2, whi.y);
        ffma2(acc[3][0], a3, wlo.x);
        ffma2(acc[3][1], a3, wlo.y);
        ffma2(acc[3][2], a3, whi.x);
        ffma2(acc[3][3], a3, whi.y);
    }
}

__device__ __forceinline__ void acc_zero(ull acc[4][4]) {
    #pragma unroll
    for (int i = 0; i < 4; i++)
        #pragma unroll
        for (int j = 0; j < 4; j++)
            acc[i][j] = 0ull;
}

// XOR-swizzled partial-z store: z(row,c) at row*32 + (c ^ (row>>2)). Conflict-free.
__device__ __forceinline__ void z_store(float* zs, int tx, int ty, const ull acc[4][4]) {
    #pragma unroll
    for (int i = 0; i < 4; i++) {
        float* zrow = zs + (tx * 4 + i) * 32;
        #pragma unroll
        for (int jp = 0; jp < 4; jp++) {
            float lo, hi;
            unpack2(acc[i][jp], lo, hi);
            int c = ty * 8 + jp * 2;
            zrow[c ^ tx] = lo;
            zrow[(c + 1) ^ tx] = hi;
        }
    }
}

// activation: thread -> (2 rows, 1 unit); FIXED mapping (c lives here)
__device__ __forceinline__ void activation(
    const float* __restrict__ zsm, const float* __restrict__ bsm,
    float c2[2], float* __restrict__ hOutT, int b0, int nb, int tid)
{
    int u  = tid >> 6;              // 0..7
    int r0 = (tid & 63) * 2;
    float hv[2];
    #pragma unroll
    for (int i = 0; i < 2; i++) {
        int r = r0 + i;
        int sw = r >> 2;            // read-side of the XOR swizzle
        float zi = bsm[u],      zf = bsm[8 + u];
        float zg = bsm[16 + u], zo = bsm[24 + u];
        #pragma unroll
        for (int p = 0; p < 4; p++) {
            const float* zp = zsm + p * (128 * 32) + r * 32;
            zi += zp[u ^ sw];
            zf += zp[(8 + u) ^ sw];
            zg += zp[(16 + u) ^ sw];
            zo += zp[(24 + u) ^ sw];
        }
        float ig = sigm(zi);
        float fg = sigm(zf);
        float gg = fmaxf(zg, 0.0f);
        float og = sigm(zo);
        float cn = fg * c2[i] + ig * gg;
        c2[i] = cn;
        hv[i] = og * fmaxf(cn, 0.0f);
    }
    *reinterpret_cast<float2*>(&hOutT[(nb * 8 + u) * BB + b0 + r0]) =
        make_float2(hv[0], hv[1]);
}

// out(tt) = h@Wo + bo : 4 out-cols x 128 rows, K split in 4 chunks, zsm scratch
__device__ __forceinline__ void outproj(
    const float* __restrict__ hbuf,   // &g_H[p][0][0] (all-visible h)
    const float* __restrict__ wosm, const float* __restrict__ bosm,
    float* __restrict__ zsm, float* __restrict__ outp,
    int b0, int nb, int tt, int tid)
{
    int b  = tid & 127;
    int qq = tid >> 7;                     // 0..3 -> K chunk of 64
    const float* hP = hbuf + (size_t)(qq * 64) * BB + b0 + b;
    const float* wP = wosm + qq * 64 * 4;
    float s0 = 0.f, s1 = 0.f, s2 = 0.f, s3 = 0.f;
    #pragma unroll 8
    for (int kk = 0; kk < 64; kk++) {
        float h = hP[(size_t)kk * BB];
        float4 w4 = *reinterpret_cast<const float4*>(wP + kk * 4);
        s0 = fmaf(h, w4.x, s0);
        s1 = fmaf(h, w4.y, s1);
        s2 = fmaf(h, w4.z, s2);
        s3 = fmaf(h, w4.w, s3);
    }
    if (qq) {
        float* zp = zsm + ((qq - 1) * 128 + b) * 4;
        zp[0] = s0; zp[1] = s1; zp[2] = s2; zp[3] = s3;
    }
    __syncthreads();
    if (qq == 0) {
        #pragma unroll
        for (int p = 0; p < 3; p++) {
            const float* zp = zsm + (p * 128 + b) * 4;
            s0 += zp[0]; s1 += zp[1]; s2 += zp[2]; s3 += zp[3];
        }
        s0 += bosm[0]; s1 += bosm[1]; s2 += bosm[2]; s3 += bosm[3];
        *reinterpret_cast<float4*>(
            outp + (size_t)(b0 + b) * (TT * DD) + tt * DD + nb * 4) =
            make_float4(s0, s1, s2, s3);
    }
    __syncthreads();   // zsm scratch protected: wait no longer has a CTA bar
}

// Tiled transpose: encIn[b][t][k] -> g_encT[t][k][b]
extern "C" __global__ void __launch_bounds__(256)
transpose_enc_kernel(const float* __restrict__ in)
{
    __shared__ float tile[32][33];
    int t  = blockIdx.z;
    int k0 = blockIdx.y * 32;
    int b0 = blockIdx.x * 32;
    int tx = threadIdx.x, ty = threadIdx.y;  // 32 x 8
    #pragma unroll
    for (int i = 0; i < 32; i += 8)
        tile[ty + i][tx] = in[(size_t)(b0 + ty + i) * (TT * DD) + t * DD + k0 + tx];
    __syncthreads();
    #pragma unroll
    for (int i = 0; i < 32; i += 8)
        g_encT[t][k0 + ty + i][b0 + tx] = tile[tx][ty + i];
}

extern "C" __global__ void __launch_bounds__(NTHR, 1)
lstm_ae_kernel(const float* __restrict__ decIn,
               const float* __restrict__ W0, const float* __restrict__ U0, const float* __restrict__ b0g,
               const float* __restrict__ W1, const float* __restrict__ U1, const float* __restrict__ b1g,
               const float* __restrict__ Wd, const float* __restrict__ Ud, const float* __restrict__ bdg,
               const float* __restrict__ Wo, const float* __restrict__ bog,
               float* __restrict__ outp)
{
    extern __shared__ float smem[];
    float* w0sm  = smem;                  // [384][32]
    float* w1sm  = w0sm + 384 * 32;       // [256][32]  (W1+U1 fused)
    float* wdxsm = w1sm + 256 * 32;       // [128][32]  x-part of Wd (decoder t=0 only)
    float* wfdsm = wdxsm + 128 * 32;      // [256][32]  FUSED Wo@Wd + Ud
    float* wosm  = wfdsm + 256 * 32;      // [256][4]
    float* b0sm  = wosm + 256 * 4;        // 32
    float* b1sm  = b0sm + 32;             // 32
    float* bdsm  = b1sm + 32;             // 32  (plain bd, t=0)
    float* bfdsm = bdsm + 32;             // 32  (bo@Wd + bd, t>=1)
    float* bosm  = bfdsm + 32;            // 4
    float* snapSm = bosm + 8;             // 1 (+pad)  smem broadcast of barrier snapshot
    float* zsm   = bosm + 16;             // [4][128][32] XOR-swizzled

    int tid = threadIdx.x;
    int nb = blockIdx.x & 31;           // hidden-unit block (8 units)
    int rb = blockIdx.x >> 5;           // row block (128 batch rows)
    int b0 = rb * 128;

    int q    = tid >> 7;                // K quarter
    int qtid = tid & 127;
    int tx   = qtid & 31;               // rows tx*4 .. +3
    int ty   = qtid >> 5;               // cols ty*8 .. +7 (warp-uniform)
    int colBase = b0 + tx * 4;
    float* zq = zsm + q * (128 * 32);
    unsigned int* snapP = reinterpret_cast<unsigned int*>(snapSm);
    const float* w0ty  = w0sm + ty * 8;
    const float* w1ty  = w1sm + ty * 8;
    const float* wdxty = wdxsm + ty * 8;
    const float* wfdty = wfdsm + ty * 8;

    // ---- one-time weight preload, layout [k][32 local cols] ----
    for (int idx = tid; idx < 384 * 32; idx += NTHR) {
        int k = idx >> 5, lc = idx & 31;
        int gcol = (lc >> 3) * LL + nb * 8 + (lc & 7);
        w0sm[idx] = (k < DD) ? W0[k * G4 + gcol] : U0[(k - DD) * G4 + gcol];
    }
    for (int idx = tid; idx < 256 * 32; idx += NTHR) {
        int k = idx >> 5, lc = idx & 31;
        int gcol = (lc >> 3) * LL + nb * 8 + (lc & 7);
        w1sm[idx] = W1[k * G4 + gcol] + U1[k * G4 + gcol];
    }
    for (int idx = tid; idx < 128 * 32; idx += NTHR) {
        int k = idx >> 5, lc = idx & 31;
        int gcol = (lc >> 3) * LL + nb * 8 + (lc & 7);
        wdxsm[idx] = Wd[k * G4 + gcol];
    }
    // FUSED decoder weight: Wfd[k][lc] = Ud[k][gcol] + sum_j Wo[k][j]*Wd[j][gcol]
    for (int idx = tid; idx < 256 * 32; idx += NTHR) {
        int k = idx >> 5, lc = idx & 31;
        int gcol = (lc >> 3) * LL + nb * 8 + (lc & 7);
        float s = Ud[k * G4 + gcol];
        const float* worow = Wo + k * DD;
        #pragma unroll 4
        for (int j = 0; j < DD; j++)
            s = fmaf(worow[j], Wd[j * G4 + gcol], s);
        wfdsm[idx] = s;
    }
    for (int idx = tid; idx < 256 * 4; idx += NTHR) {
        int k = idx >> 2, j = idx & 3;
        wosm[idx] = Wo[k * DD + nb * 4 + j];
    }
    if (tid < 32) {
        int gcol = (tid >> 3) * LL + nb * 8 + (tid & 7);
        b0sm[tid] = b0g[gcol];
        b1sm[tid] = b1g[gcol];
        bdsm[tid] = bdg[gcol];
        float s = bdg[gcol];
        #pragma unroll 4
        for (int j = 0; j < DD; j++)
            s = fmaf(bog[j], Wd[j * G4 + gcol], s);
        bfdsm[tid] = s;
    }
    if (tid < 4) bosm[tid] = bog[nb * 4 + tid];

    // init: zero h buffer 0; stage decoder x(0) transposed
    for (int idx = tid; idx < 8 * 128; idx += NTHR) {
        int f = idx >> 7, b = idx & 127;
        g_H[0][nb * 8 + f][b0 + b] = 0.0f;
    }
    for (int idx = tid; idx < 4 * 128; idx += NTHR) {
        int f = idx >> 7, b = idx & 127;
        g_x0T[nb * 4 + f][b0 + b] = decIn[(size_t)(b0 + b) * (TT * DD) + nb * 4 + f];
    }
    __syncthreads();   // weights visible before prologue x-gemm

    float c2[2] = {0.0f, 0.0f};

    // x-partials for encoder t=0 accumulate in registers (depends only on g_encT)
    ull acc[4][4];
    acc_zero(acc);
    gemm48(&g_encT[0][q * 32][colBase], w0ty + (q * 32) * 32, 32, acc);

    // arrive wrapper: thread0 snapshots into smem for the all-thread wait.
    // snapshot store is ordered before the next wait by arrive's __syncthreads
    // (in rb_arrive) happening BEFORE... (snap written after atomic; need a CTA
    // sync before other threads read it in rb_wait) -> write snap, then bar.
    unsigned int snap0;
    rb_arrive(rb, &snap0);
    if (tid == 0) *snapP = snap0;
    __syncthreads();                      // snap visible to all threads
    rb_wait(rb, snapP);                   // init barrier (H, x0 visible)

    int cur = 0;
    // ---------------- encoder (triple-buffered h) ----------------
    for (int t = 0; t < TT; t++) {
        int nx;
        // ===== layer 0: acc already holds x_t @ W0 partials =====
        gemm48(&g_H[cur][q * 64][colBase], w0ty + (DD + q * 64) * 32, 64, acc);
        z_store(zq, tx, ty, acc);
        __syncthreads();
        nx = cur + 1; if (nx == 3) nx = 0;
        activation(zsm, b0sm, c2, &g_H[nx][0][0], b0, nb, tid);
        rb_arrive(rb, &snap0);                     // h_L0(t) posted
        if (tid == 0) *snapP = snap0;
        __syncthreads();
        cur = nx;
        rb_wait(rb, snapP);                        // h_L0(t) all visible

        // ===== layer 1: z = h' @ (W1+U1) =====
        acc_zero(acc);
        gemm48(&g_H[cur][q * 64][colBase], w1ty + (q * 64) * 32, 64, acc);
        z_store(zq, tx, ty, acc);
        __syncthreads();
        nx = cur + 1; if (nx == 3) nx = 0;
        activation(zsm, b1sm, c2, &g_H[nx][0][0], b0, nb, tid);
        rb_arrive(rb, &snap0);                     // h_L1(t) posted
        if (tid == 0) *snapP = snap0;
        __syncthreads();
        cur = nx;

        // ===== overlap: next step's x-partials in registers while barrier settles
        acc_zero(acc);
        if (t + 1 < TT)
            gemm48(&g_encT[t + 1][q * 32][colBase], w0ty + (q * 32) * 32, 32, acc);
        rb_wait(rb, snapP);                        // h_L1(t) all visible
    }

    // ---------------- decoder: ONE barrier per step (fused recurrence) ----------
    // z(t) = h(t-1) @ Wfd + bfd   for t>=1;  t=0 uses x0@Wd + h_enc@Ud + bd.
    for (int t = 0; t < TT; t++) {
        acc_zero(acc);
        if (t == 0) {
            gemm48(&g_x0T[q * 32][colBase], wdxty + (q * 32) * 32, 32, acc);
            gemm48g(&g_H[cur][q * 64][colBase],
                    Ud + (size_t)(q * 64) * G4 + ty * LL + nb * 8, 64, acc);
        } else {
            gemm48(&g_H[cur][q * 64][colBase], wfdty + (q * 64) * 32, 64, acc);
        }
        z_store(zq, tx, ty, acc);
        __syncthreads();
        int nx = cur + 1; if (nx == 3) nx = 0;
        activation(zsm, (t == 0) ? bdsm : bfdsm, c2, &g_H[nx][0][0], b0, nb, tid);
        rb_arrive(rb, &snap0);                     // h(t) posted
        if (tid == 0) *snapP = snap0;
        // (outproj's first __syncthreads makes snapP visible before rb_wait)
        // ===== shadow: out(t-1) = h(t-1)@Wo + bo (buf[cur] still safe: 3 buffers)
        if (t >= 1) {
            outproj(&g_H[cur][0][0], wosm, bosm, zsm, outp, b0, nb, t - 1, tid);
        } else {
            __syncthreads();
        }
        cur = nx;
        rb_wait(rb, snapP);                        // h(t) all visible
    }
    // epilogue: out(511) needs all h(511) (already waited)
    outproj(&g_H[cur][0][0], wosm, bosm, zsm, outp, b0, nb, TT - 1, tid);
}

extern "C" void kernel_launch(void* const* d_in, const int* in_sizes, int n_in,
                              void* d_out, int out_size)
{
    const float* encIn = (const float*)d_in[0];
    const float* decIn = (const float*)d_in[1];
    const float* W0    = (const float*)d_in[2];
    const float* U0    = (const float*)d_in[3];
    const float* b0    = (const float*)d_in[4];
    const float* W1    = (const float*)d_in[5];
    const float* U1    = (const float*)d_in[6];
    const float* b1    = (const float*)d_in[7];
    const float* Wd    = (const float*)d_in[8];
    const float* Ud    = (const float*)d_in[9];
    const float* bd    = (const float*)d_in[10];
    const float* Wo    = (const float*)d_in[11];
    const float* bo    = (const float*)d_in[12];
    float* outp = (float*)d_out;

    // 1) transpose encoder inputs
    {
        dim3 grid(BB / 32, DD / 32, TT);
        dim3 block(32, 8);
        transpose_enc_kernel<<<grid, block>>>(encIn);
    }

    // 2) persistent LSTM kernel
    // smem floats: 12288+8192+4096+8192+1024+128+16 + 4*128*32 = 50320 (201.3KB)
    size_t smem_bytes = 50320 * sizeof(float);
    cudaFuncSetAttribute((const void*)lstm_ae_kernel,
                         cudaFuncAttributeMaxDynamicSharedMemorySize, (int)smem_bytes);
    lstm_ae_kernel<<<NCTA, NTHR, smem_bytes>>>(
        decIn, W0, U0, b0, W1, U1, b1, Wd, Ud, bd, Wo, bo, outp);
}